// round 7
// baseline (speedup 1.0000x reference)
#include <cuda_runtime.h>
#include <cfloat>
#include <stdint.h>
#include <math.h>

// ---------------------------------------------------------------------------
// FocalLoss (RetinaNet) fully-fused single-kernel for GB300, v6.
//   - packed single-scalar IoU argmax: r = inter * rcp.approx(S) is monotone
//     with iou; pack r-bits with inverted index, reduce with one IMNMX
//     (loop-carried chain 20+ cyc -> 4 cyc)
//   - precise inter/ua division recomputed once for the selected GT so the
//     0.4 / 0.5 threshold decisions match the reference
//   - branch-free focal cls sum: sqrt.approx + lg2 MUFU, ln2 folded once
//   - last-block-done finalize + accumulator reset (single launch)
// ---------------------------------------------------------------------------

#define TPB 256
#define M_MAX 64
#define B_MAX 32
#define LN2F 0.6931471805599453f

__device__ double g_cs[B_MAX];
__device__ double g_rs[B_MAX];
__device__ int    g_np[B_MAX];
__device__ int    g_arrive = 0;

__device__ __forceinline__ float frcp(float x) {
    float r; asm("rcp.approx.f32 %0, %1;" : "=f"(r) : "f"(x)); return r;
}
__device__ __forceinline__ float fsqrt_ap(float x) {
    float r; asm("sqrt.approx.f32 %0, %1;" : "=f"(r) : "f"(x)); return r;
}

template <int MT, int CT>
__global__ void __launch_bounds__(TPB, 5)
fl_kernel(const float* __restrict__ cls,
          const float* __restrict__ reg,
          const float* __restrict__ anc,
          const float* __restrict__ ann,
          float* __restrict__ out,
          int A, int C, int M, int B, int nblocks)
{
    __shared__ float4 sbox[M_MAX];   // (x1, y1, x2, y2)
    __shared__ float  sarea[M_MAX];
    __shared__ int    slbl[M_MAX];
    __shared__ bool   s_last;

    const int b   = blockIdx.y;
    const int tid = threadIdx.x;
    const int MM  = MT ? MT : M;
    const unsigned FULL = 0xFFFFFFFFu;

    // ---- load GT boxes (invalid -> degenerate zero box, never selected) ----
    if (tid < MM) {
        const float* g = ann + ((size_t)b * MM + tid) * 5;
        float x1 = g[0], y1 = g[1], x2 = g[2], y2 = g[3];
        const float l = g[4];
        if (l == -1.0f) { x1 = 0.f; y1 = 0.f; x2 = 0.f; y2 = 0.f; }
        sbox[tid]  = make_float4(x1, y1, x2, y2);
        sarea[tid] = (x2 - x1) * (y2 - y1);
        slbl[tid]  = (int)l;
    }
    __syncthreads();

    const int a = blockIdx.x * TPB + tid;

    float cls_acc = 0.0f;
    float reg_acc = 0.0f;
    int   pos_i   = 0;

    if (a < A) {
        const float4 ab = ((const float4*)anc)[a];
        const float aw = ab.z - ab.x;
        const float ah = ab.w - ab.y;
        const float area_a = aw * ah;

        // Prefetch classification row (overlaps DRAM latency with IoU loop).
        float4 c0, c1, c2, c3, c4;
        const float* cp = cls + ((size_t)b * A + a) * (CT ? CT : C);
        if (CT == 20) {
            const float4* cp4 = (const float4*)cp;
            c0 = cp4[0]; c1 = cp4[1]; c2 = cp4[2]; c3 = cp4[3]; c4 = cp4[4];
        }

        // --- IoU argmax: iou = r/(1-r) monotone in r = inter/S, so ordering
        //     by r orders by iou. Pack r bits (>=0) with inverted index; a
        //     single unsigned max carries the loop (4-cyc chain). ---
        unsigned bestv = 0u;
        #pragma unroll
        for (int m = 0; m < MM; m++) {
            const float4 g = sbox[m];
            const float iw = fminf(ab.z, g.z) - fmaxf(ab.x, g.x);
            const float ih = fminf(ab.w, g.w) - fmaxf(ab.y, g.y);
            const float inter = fmaxf(iw, 0.0f) * fmaxf(ih, 0.0f);
            const float S = area_a + sarea[m];
            const float r = inter * frcp(S);
            const unsigned v = (__float_as_uint(r) & 0xFFFFFFE0u)
                             | (unsigned)(31 - m);
            bestv = (v > bestv) ? v : bestv;    // IMNMX.U32
        }
        const int arg = 31 - (int)(bestv & 31u);

        // Precise recompute for the selected GT (threshold fidelity).
        const float4 gb = sbox[arg];
        const float sab = sarea[arg];
        const float iwb = fminf(ab.z, gb.z) - fmaxf(ab.x, gb.x);
        const float ihb = fminf(ab.w, gb.w) - fmaxf(ab.y, gb.y);
        const float interb = fmaxf(iwb, 0.0f) * fmaxf(ihb, 0.0f);
        const float uab = area_a + sab - interb;       // >= area_a >= 256
        const float best = interb / uab;               // one precise division
        const bool  pos  = (best >= 0.5f);
        const bool  contrib = pos || (best < 0.4f);

        // --- branch-free focal: s = sum p^1.5 * lg2(1-p) over classes ---
        float s = 0.0f;
        if (CT == 20) {
            const float pv[20] = {c0.x,c0.y,c0.z,c0.w, c1.x,c1.y,c1.z,c1.w,
                                  c2.x,c2.y,c2.z,c2.w, c3.x,c3.y,c3.z,c3.w,
                                  c4.x,c4.y,c4.z,c4.w};
            #pragma unroll
            for (int c = 0; c < 20; c++) {
                const float p = pv[c];
                s = fmaf(p * fsqrt_ap(p), __log2f(1.0f - p), s);
            }
        } else {
            for (int c = 0; c < C; c++) {
                const float p = fminf(fmaxf(cp[c], 1e-8f), 1.0f - 1e-8f);
                s = fmaf(p * fsqrt_ap(p), __log2f(1.0f - p), s);
            }
        }
        cls_acc = contrib ? (-0.8f * LN2F) * s : 0.0f;

        if (pos) {
            pos_i = 1;
            const int lbl = slbl[arg];
            const float pl = cp[lbl];                  // L1/L2-hot reload
            const float ql = 1.0f - pl;
            // remove the label's negative term, add its positive term
            const float base = s - pl * fsqrt_ap(pl) * __log2f(ql);
            const float post = ql * fsqrt_ap(ql) * __log2f(pl);
            cls_acc = -LN2F * (0.8f * base + 0.2f * post);

            // --- smooth-L1 regression loss ---
            const float gwr = gb.z - gb.x, ghr = gb.w - gb.y;
            const float gcx = gb.x + 0.5f * gwr;
            const float gcy = gb.y + 0.5f * ghr;
            const float gw  = fmaxf(gwr, 1.0f);
            const float gh  = fmaxf(ghr, 1.0f);
            const float acx = ab.x + 0.5f * aw;
            const float acy = ab.y + 0.5f * ah;

            const float t0 = ((gcx - acx) / aw) / 0.1f;
            const float t1 = ((gcy - acy) / ah) / 0.1f;
            const float t2 = logf(gw / aw) / 0.2f;
            const float t3 = logf(gh / ah) / 0.2f;

            const float4 rg = ((const float4*)reg)[(size_t)b * A + a];

            const float thr = 1.0f / 9.0f;
            const float off = 0.5f / 9.0f;
            float sr = 0.0f, d;
            d = fabsf(t0 - rg.x); sr += (d <= thr) ? 4.5f * d * d : d - off;
            d = fabsf(t1 - rg.y); sr += (d <= thr) ? 4.5f * d * d : d - off;
            d = fabsf(t2 - rg.z); sr += (d <= thr) ? 4.5f * d * d : d - off;
            d = fabsf(t3 - rg.w); sr += (d <= thr) ? 4.5f * d * d : d - off;
            reg_acc = sr;
        }
    }

    // ---- block reduction: warp shuffle -> shared -> fp64 atomics ----
    #pragma unroll
    for (int o = 16; o > 0; o >>= 1) {
        cls_acc += __shfl_down_sync(FULL, cls_acc, o);
        reg_acc += __shfl_down_sync(FULL, reg_acc, o);
        pos_i   += __shfl_down_sync(FULL, pos_i,   o);
    }

    __shared__ float wc[TPB / 32], wr[TPB / 32];
    __shared__ int   wp[TPB / 32];
    const int wid = tid >> 5;
    const int lid = tid & 31;
    if (lid == 0) { wc[wid] = cls_acc; wr[wid] = reg_acc; wp[wid] = pos_i; }
    __syncthreads();

    if (tid < 32) {
        const int nwarp = TPB / 32;
        float csum = (lid < nwarp) ? wc[lid] : 0.0f;
        float rsum = (lid < nwarp) ? wr[lid] : 0.0f;
        int   psum = (lid < nwarp) ? wp[lid] : 0;
        #pragma unroll
        for (int o = 4; o > 0; o >>= 1) {
            csum += __shfl_down_sync(FULL, csum, o);
            rsum += __shfl_down_sync(FULL, rsum, o);
            psum += __shfl_down_sync(FULL, psum, o);
        }
        if (lid == 0) {
            if (csum != 0.0f) atomicAdd(&g_cs[b], (double)csum);
            if (rsum != 0.0f) atomicAdd(&g_rs[b], (double)rsum);
            if (psum != 0)    atomicAdd(&g_np[b], psum);
            __threadfence();
            const int prev = atomicAdd(&g_arrive, 1);
            s_last = (prev == nblocks - 1);
        }
    }
    __syncthreads();

    // ---- last block finalizes the output and resets the accumulators ----
    if (s_last && tid < 32) {
        float cl = 0.0f, rl = 0.0f;
        if (tid < B) {
            int nvv = 0;
            for (int m = 0; m < M; m++)
                nvv += (ann[((size_t)tid * M + m) * 5 + 4] != -1.0f) ? 1 : 0;
            const int np = g_np[tid];
            const float npf = (float)np;
            cl = (float)g_cs[tid] / fmaxf(npf, 1.0f);
            rl = (float)g_rs[tid] / fmaxf(4.0f * npf, 1.0f);
            if (np == 0) rl = 0.0f;
            if (nvv == 0) { cl = 0.0f; rl = 0.0f; }
        }
        #pragma unroll
        for (int o = 16; o > 0; o >>= 1) {
            cl += __shfl_down_sync(FULL, cl, o);
            rl += __shfl_down_sync(FULL, rl, o);
        }
        if (tid == 0) {
            out[0] = cl / (float)B;
            out[1] = rl / (float)B;
        }
        g_cs[tid] = 0.0;
        g_rs[tid] = 0.0;
        g_np[tid] = 0;
        if (tid == 0) g_arrive = 0;
    }
}

extern "C" void kernel_launch(void* const* d_in, const int* in_sizes, int n_in,
                              void* d_out, int out_size)
{
    const float* cls = (const float*)d_in[0];
    const float* reg = (const float*)d_in[1];
    const float* anc = (const float*)d_in[2];
    const float* ann = (const float*)d_in[3];
    float* out = (float*)d_out;

    const int A = in_sizes[2] / 4;            // anchors [1,A,4]
    const int B = in_sizes[1] / (A * 4);      // regressions [B,A,4]
    const int C = in_sizes[0] / (B * A);      // classifications [B,A,C]
    const int M = in_sizes[3] / (B * 5);      // annotations [B,M,5]

    dim3 block(TPB);
    dim3 grid((A + TPB - 1) / TPB, B);
    const int nblocks = grid.x * grid.y;

    if (M == 32 && C == 20)
        fl_kernel<32, 20><<<grid, block>>>(cls, reg, anc, ann, out, A, C, M, B, nblocks);
    else
        fl_kernel<0, 0><<<grid, block>>>(cls, reg, anc, ann, out, A, C, M, B, nblocks);
}

// round 8
// speedup vs baseline: 1.1066x; 1.1066x over previous
#include <cuda_runtime.h>
#include <cfloat>
#include <stdint.h>
#include <math.h>

// ---------------------------------------------------------------------------
// FocalLoss (RetinaNet) fully-fused single-kernel for GB300, v8.
//   v5 core (best known: FSETP/FSEL argmax, cancelled cross-multiply) plus:
//   - no register-resident cls prefetch: stream 5x float4, consume at once
//     (cuts ~20 live registers)
//   - __launch_bounds__(256, 6): occupancy 57% -> 75%, more eligible warps
//     per SMSP to fill alu-pipe issue slots
// ---------------------------------------------------------------------------

#define TPB 256
#define M_MAX 64
#define B_MAX 32

__device__ double g_cs[B_MAX];
__device__ double g_rs[B_MAX];
__device__ int    g_np[B_MAX];
__device__ int    g_arrive = 0;

template <int MT, int CT>
__global__ void __launch_bounds__(TPB, 6)
fl_kernel(const float* __restrict__ cls,
          const float* __restrict__ reg,
          const float* __restrict__ anc,
          const float* __restrict__ ann,
          float* __restrict__ out,
          int A, int C, int M, int B, int nblocks)
{
    __shared__ float4 sbox[M_MAX];   // (x1, y1, x2, y2)
    __shared__ float  sarea[M_MAX];
    __shared__ int    slbl[M_MAX];
    __shared__ bool   s_last;

    const int b   = blockIdx.y;
    const int tid = threadIdx.x;
    const int MM  = MT ? MT : M;
    const unsigned FULL = 0xFFFFFFFFu;

    // ---- load GT boxes (invalid -> degenerate zero box, never selected) ----
    if (tid < MM) {
        const float* g = ann + ((size_t)b * MM + tid) * 5;
        float x1 = g[0], y1 = g[1], x2 = g[2], y2 = g[3];
        const float l = g[4];
        if (l == -1.0f) { x1 = 0.f; y1 = 0.f; x2 = 0.f; y2 = 0.f; }
        sbox[tid]  = make_float4(x1, y1, x2, y2);
        sarea[tid] = (x2 - x1) * (y2 - y1);
        slbl[tid]  = (int)l;
    }
    __syncthreads();

    const int a = blockIdx.x * TPB + tid;

    float cls_acc = 0.0f;
    float reg_acc = 0.0f;
    int   pos_i   = 0;

    if (a < A) {
        const float4 ab = ((const float4*)anc)[a];
        const float aw = ab.z - ab.x;
        const float ah = ab.w - ab.y;
        const float area_a = aw * ah;

        // --- IoU max/argmax, cancelled cross-multiply compare ---
        // iou_m = inter_m / (S_m - inter_m), S_m = area_a + area_b[m]
        // iou_i > iou_j  <=>  inter_i*S_j > inter_j*S_i
        float binter = 0.0f;
        float bS     = 1.0f;
        int   arg    = 0;
        #pragma unroll
        for (int m = 0; m < MM; m++) {
            const float4 g = sbox[m];
            const float iw = fminf(ab.z, g.z) - fmaxf(ab.x, g.x);
            const float ih = fminf(ab.w, g.w) - fmaxf(ab.y, g.y);
            const float inter = fmaxf(iw, 0.0f) * fmaxf(ih, 0.0f);
            const float S = area_a + sarea[m];
            if (inter * bS > binter * S) {
                binter = inter; bS = S; arg = m;
            }
        }
        const float best = binter / (bS - binter);    // one precise division
        const bool  pos  = (best >= 0.5f);

        if (pos || best < 0.4f) {
            const float* cp = cls + ((size_t)b * A + a) * (CT ? CT : C);

            // Focal negative term for all classes, streamed float4-at-a-time
            // (short register live ranges; occupancy covers DRAM latency).
            float s = 0.0f;
            if (CT == 20) {
                const float4* cp4 = (const float4*)cp;
                #pragma unroll
                for (int i = 0; i < 5; i++) {
                    const float4 v = cp4[i];
                    float p;
                    p = v.x; s = fmaf(p * p * rsqrtf(p), __logf(1.0f - p), s);
                    p = v.y; s = fmaf(p * p * rsqrtf(p), __logf(1.0f - p), s);
                    p = v.z; s = fmaf(p * p * rsqrtf(p), __logf(1.0f - p), s);
                    p = v.w; s = fmaf(p * p * rsqrtf(p), __logf(1.0f - p), s);
                }
            } else {
                for (int c = 0; c < C; c++) {
                    const float p = fminf(fmaxf(cp[c], 1e-8f), 1.0f - 1e-8f);
                    s = fmaf(p * p * rsqrtf(p), __logf(1.0f - p), s);
                }
            }
            cls_acc = -0.8f * s;

            if (pos) {
                pos_i = 1;
                const int lbl = slbl[arg];
                const float pl = cp[lbl];                 // L1-hot reload
                const float ql = 1.0f - pl;
                const float fneg = pl * pl * rsqrtf(pl) * (-__logf(ql));
                const float fpos = ql * ql * rsqrtf(ql) * (-__logf(pl));
                cls_acc += 0.2f * fpos - 0.8f * fneg;

                // --- smooth-L1 regression loss ---
                const float4 gb = sbox[arg];
                const float gwr = gb.z - gb.x, ghr = gb.w - gb.y;
                const float gcx = gb.x + 0.5f * gwr;
                const float gcy = gb.y + 0.5f * ghr;
                const float gw  = fmaxf(gwr, 1.0f);
                const float gh  = fmaxf(ghr, 1.0f);
                const float acx = ab.x + 0.5f * aw;
                const float acy = ab.y + 0.5f * ah;

                const float t0 = ((gcx - acx) / aw) / 0.1f;
                const float t1 = ((gcy - acy) / ah) / 0.1f;
                const float t2 = logf(gw / aw) / 0.2f;
                const float t3 = logf(gh / ah) / 0.2f;

                const float4 rg = ((const float4*)reg)[(size_t)b * A + a];

                const float thr = 1.0f / 9.0f;
                const float off = 0.5f / 9.0f;
                float sr = 0.0f, d;
                d = fabsf(t0 - rg.x); sr += (d <= thr) ? 4.5f * d * d : d - off;
                d = fabsf(t1 - rg.y); sr += (d <= thr) ? 4.5f * d * d : d - off;
                d = fabsf(t2 - rg.z); sr += (d <= thr) ? 4.5f * d * d : d - off;
                d = fabsf(t3 - rg.w); sr += (d <= thr) ? 4.5f * d * d : d - off;
                reg_acc = sr;
            }
        }
    }

    // ---- block reduction: warp shuffle -> shared -> fp64 atomics ----
    #pragma unroll
    for (int o = 16; o > 0; o >>= 1) {
        cls_acc += __shfl_down_sync(FULL, cls_acc, o);
        reg_acc += __shfl_down_sync(FULL, reg_acc, o);
        pos_i   += __shfl_down_sync(FULL, pos_i,   o);
    }

    __shared__ float wc[TPB / 32], wr[TPB / 32];
    __shared__ int   wp[TPB / 32];
    const int wid = tid >> 5;
    const int lid = tid & 31;
    if (lid == 0) { wc[wid] = cls_acc; wr[wid] = reg_acc; wp[wid] = pos_i; }
    __syncthreads();

    if (tid < 32) {
        const int nwarp = TPB / 32;
        float csum = (lid < nwarp) ? wc[lid] : 0.0f;
        float rsum = (lid < nwarp) ? wr[lid] : 0.0f;
        int   psum = (lid < nwarp) ? wp[lid] : 0;
        #pragma unroll
        for (int o = 4; o > 0; o >>= 1) {
            csum += __shfl_down_sync(FULL, csum, o);
            rsum += __shfl_down_sync(FULL, rsum, o);
            psum += __shfl_down_sync(FULL, psum, o);
        }
        if (lid == 0) {
            if (csum != 0.0f) atomicAdd(&g_cs[b], (double)csum);
            if (rsum != 0.0f) atomicAdd(&g_rs[b], (double)rsum);
            if (psum != 0)    atomicAdd(&g_np[b], psum);
            __threadfence();
            const int prev = atomicAdd(&g_arrive, 1);
            s_last = (prev == nblocks - 1);
        }
    }
    __syncthreads();

    // ---- last block finalizes the output and resets the accumulators ----
    if (s_last && tid < 32) {
        float cl = 0.0f, rl = 0.0f;
        if (tid < B) {
            int nvv = 0;
            for (int m = 0; m < M; m++)
                nvv += (ann[((size_t)tid * M + m) * 5 + 4] != -1.0f) ? 1 : 0;
            const int np = g_np[tid];
            const float npf = (float)np;
            cl = (float)g_cs[tid] / fmaxf(npf, 1.0f);
            rl = (float)g_rs[tid] / fmaxf(4.0f * npf, 1.0f);
            if (np == 0) rl = 0.0f;
            if (nvv == 0) { cl = 0.0f; rl = 0.0f; }
        }
        #pragma unroll
        for (int o = 16; o > 0; o >>= 1) {
            cl += __shfl_down_sync(FULL, cl, o);
            rl += __shfl_down_sync(FULL, rl, o);
        }
        if (tid == 0) {
            out[0] = cl / (float)B;
            out[1] = rl / (float)B;
        }
        g_cs[tid] = 0.0;
        g_rs[tid] = 0.0;
        g_np[tid] = 0;
        if (tid == 0) g_arrive = 0;
    }
}

extern "C" void kernel_launch(void* const* d_in, const int* in_sizes, int n_in,
                              void* d_out, int out_size)
{
    const float* cls = (const float*)d_in[0];
    const float* reg = (const float*)d_in[1];
    const float* anc = (const float*)d_in[2];
    const float* ann = (const float*)d_in[3];
    float* out = (float*)d_out;

    const int A = in_sizes[2] / 4;            // anchors [1,A,4]
    const int B = in_sizes[1] / (A * 4);      // regressions [B,A,4]
    const int C = in_sizes[0] / (B * A);      // classifications [B,A,C]
    const int M = in_sizes[3] / (B * 5);      // annotations [B,M,5]

    dim3 block(TPB);
    dim3 grid((A + TPB - 1) / TPB, B);
    const int nblocks = grid.x * grid.y;

    if (M == 32 && C == 20)
        fl_kernel<32, 20><<<grid, block>>>(cls, reg, anc, ann, out, A, C, M, B, nblocks);
    else
        fl_kernel<0, 0><<<grid, block>>>(cls, reg, anc, ann, out, A, C, M, B, nblocks);
}

// round 9
// speedup vs baseline: 1.1556x; 1.0444x over previous
#include <cuda_runtime.h>
#include <cfloat>
#include <stdint.h>
#include <math.h>

// ---------------------------------------------------------------------------
// FocalLoss (RetinaNet) fully-fused single-kernel for GB300, v9.
//   v8 core (FSETP/FSEL argmax, streamed cls, 6 blocks/SM) plus:
//   - focal in lg2 domain: p*sqrt.approx(p)*lg2(1-p), single -0.8*ln2 scale
//     (7 -> 5 instrs per class)
//   - branch-free focal (mask with FSEL; every warp ran it anyway)
//   - REDUX.SUM for the positive count
// ---------------------------------------------------------------------------

#define TPB 256
#define M_MAX 64
#define B_MAX 32
#define LN2F 0.69314718055994530942f

__device__ double g_cs[B_MAX];
__device__ double g_rs[B_MAX];
__device__ int    g_np[B_MAX];
__device__ int    g_arrive = 0;

__device__ __forceinline__ float fsqrt_ap(float x) {
    float r; asm("sqrt.approx.f32 %0, %1;" : "=f"(r) : "f"(x)); return r;
}

template <int MT, int CT>
__global__ void __launch_bounds__(TPB, 6)
fl_kernel(const float* __restrict__ cls,
          const float* __restrict__ reg,
          const float* __restrict__ anc,
          const float* __restrict__ ann,
          float* __restrict__ out,
          int A, int C, int M, int B, int nblocks)
{
    __shared__ float4 sbox[M_MAX];   // (x1, y1, x2, y2)
    __shared__ float  sarea[M_MAX];
    __shared__ int    slbl[M_MAX];
    __shared__ bool   s_last;

    const int b   = blockIdx.y;
    const int tid = threadIdx.x;
    const int MM  = MT ? MT : M;
    const unsigned FULL = 0xFFFFFFFFu;

    // ---- load GT boxes (invalid -> degenerate zero box, never selected) ----
    if (tid < MM) {
        const float* g = ann + ((size_t)b * MM + tid) * 5;
        float x1 = g[0], y1 = g[1], x2 = g[2], y2 = g[3];
        const float l = g[4];
        if (l == -1.0f) { x1 = 0.f; y1 = 0.f; x2 = 0.f; y2 = 0.f; }
        sbox[tid]  = make_float4(x1, y1, x2, y2);
        sarea[tid] = (x2 - x1) * (y2 - y1);
        slbl[tid]  = (int)l;
    }
    __syncthreads();

    const int a = blockIdx.x * TPB + tid;

    float cls_acc = 0.0f;
    float reg_acc = 0.0f;
    int   pos_i   = 0;

    if (a < A) {
        const float4 ab = ((const float4*)anc)[a];
        const float aw = ab.z - ab.x;
        const float ah = ab.w - ab.y;
        const float area_a = aw * ah;

        const float* cp = cls + ((size_t)b * A + a) * (CT ? CT : C);

        // --- IoU max/argmax, cancelled cross-multiply compare ---
        // iou_m = inter_m / (S_m - inter_m), S_m = area_a + area_b[m]
        // iou_i > iou_j  <=>  inter_i*S_j > inter_j*S_i
        float binter = 0.0f;
        float bS     = 1.0f;
        int   arg    = 0;
        #pragma unroll
        for (int m = 0; m < MM; m++) {
            const float4 g = sbox[m];
            const float iw = fminf(ab.z, g.z) - fmaxf(ab.x, g.x);
            const float ih = fminf(ab.w, g.w) - fmaxf(ab.y, g.y);
            const float inter = fmaxf(iw, 0.0f) * fmaxf(ih, 0.0f);
            const float S = area_a + sarea[m];
            if (inter * bS > binter * S) {
                binter = inter; bS = S; arg = m;
            }
        }
        const float best = binter / (bS - binter);    // one precise division
        const bool  pos  = (best >= 0.5f);
        const bool  contrib = pos || (best < 0.4f);

        // --- branch-free focal: s = sum p*sqrt(p) * lg2(1-p), scale once ---
        float s = 0.0f;
        if (CT == 20) {
            const float4* cp4 = (const float4*)cp;
            #pragma unroll
            for (int i = 0; i < 5; i++) {
                const float4 v = cp4[i];
                float p;
                p = v.x; s = fmaf(p * fsqrt_ap(p), __log2f(1.0f - p), s);
                p = v.y; s = fmaf(p * fsqrt_ap(p), __log2f(1.0f - p), s);
                p = v.z; s = fmaf(p * fsqrt_ap(p), __log2f(1.0f - p), s);
                p = v.w; s = fmaf(p * fsqrt_ap(p), __log2f(1.0f - p), s);
            }
        } else {
            for (int c = 0; c < C; c++) {
                const float p = fminf(fmaxf(cp[c], 1e-8f), 1.0f - 1e-8f);
                s = fmaf(p * fsqrt_ap(p), __log2f(1.0f - p), s);
            }
        }
        cls_acc = contrib ? (-0.8f * LN2F) * s : 0.0f;

        if (pos) {
            pos_i = 1;
            const int lbl = slbl[arg];
            const float pl = cp[lbl];                  // L1-hot reload
            const float ql = 1.0f - pl;
            // remove the label's negative lg2-term, add its positive term
            const float base = s - pl * fsqrt_ap(pl) * __log2f(ql);
            const float post = ql * fsqrt_ap(ql) * __log2f(pl);
            cls_acc = -LN2F * fmaf(0.8f, base, 0.2f * post);

            // --- smooth-L1 regression loss ---
            const float4 gb = sbox[arg];
            const float gwr = gb.z - gb.x, ghr = gb.w - gb.y;
            const float gcx = gb.x + 0.5f * gwr;
            const float gcy = gb.y + 0.5f * ghr;
            const float gw  = fmaxf(gwr, 1.0f);
            const float gh  = fmaxf(ghr, 1.0f);
            const float acx = ab.x + 0.5f * aw;
            const float acy = ab.y + 0.5f * ah;

            const float t0 = ((gcx - acx) / aw) / 0.1f;
            const float t1 = ((gcy - acy) / ah) / 0.1f;
            const float t2 = logf(gw / aw) / 0.2f;
            const float t3 = logf(gh / ah) / 0.2f;

            const float4 rg = ((const float4*)reg)[(size_t)b * A + a];

            const float thr = 1.0f / 9.0f;
            const float off = 0.5f / 9.0f;
            float sr = 0.0f, d;
            d = fabsf(t0 - rg.x); sr += (d <= thr) ? 4.5f * d * d : d - off;
            d = fabsf(t1 - rg.y); sr += (d <= thr) ? 4.5f * d * d : d - off;
            d = fabsf(t2 - rg.z); sr += (d <= thr) ? 4.5f * d * d : d - off;
            d = fabsf(t3 - rg.w); sr += (d <= thr) ? 4.5f * d * d : d - off;
            reg_acc = sr;
        }
    }

    // ---- block reduction: warp shuffle/REDUX -> shared -> fp64 atomics ----
    #pragma unroll
    for (int o = 16; o > 0; o >>= 1) {
        cls_acc += __shfl_down_sync(FULL, cls_acc, o);
        reg_acc += __shfl_down_sync(FULL, reg_acc, o);
    }
    pos_i = __reduce_add_sync(FULL, (unsigned)pos_i);

    __shared__ float wc[TPB / 32], wr[TPB / 32];
    __shared__ int   wp[TPB / 32];
    const int wid = tid >> 5;
    const int lid = tid & 31;
    if (lid == 0) { wc[wid] = cls_acc; wr[wid] = reg_acc; wp[wid] = pos_i; }
    __syncthreads();

    if (tid < 32) {
        const int nwarp = TPB / 32;
        float csum = (lid < nwarp) ? wc[lid] : 0.0f;
        float rsum = (lid < nwarp) ? wr[lid] : 0.0f;
        int   psum = (lid < nwarp) ? wp[lid] : 0;
        #pragma unroll
        for (int o = 4; o > 0; o >>= 1) {
            csum += __shfl_down_sync(FULL, csum, o);
            rsum += __shfl_down_sync(FULL, rsum, o);
        }
        psum = __reduce_add_sync(FULL, (unsigned)psum);
        if (lid == 0) {
            if (csum != 0.0f) atomicAdd(&g_cs[b], (double)csum);
            if (rsum != 0.0f) atomicAdd(&g_rs[b], (double)rsum);
            if (psum != 0)    atomicAdd(&g_np[b], psum);
            __threadfence();
            const int prev = atomicAdd(&g_arrive, 1);
            s_last = (prev == nblocks - 1);
        }
    }
    __syncthreads();

    // ---- last block finalizes the output and resets the accumulators ----
    if (s_last && tid < 32) {
        float cl = 0.0f, rl = 0.0f;
        if (tid < B) {
            int nvv = 0;
            for (int m = 0; m < M; m++)
                nvv += (ann[((size_t)tid * M + m) * 5 + 4] != -1.0f) ? 1 : 0;
            const int np = g_np[tid];
            const float npf = (float)np;
            cl = (float)g_cs[tid] / fmaxf(npf, 1.0f);
            rl = (float)g_rs[tid] / fmaxf(4.0f * npf, 1.0f);
            if (np == 0) rl = 0.0f;
            if (nvv == 0) { cl = 0.0f; rl = 0.0f; }
        }
        #pragma unroll
        for (int o = 16; o > 0; o >>= 1) {
            cl += __shfl_down_sync(FULL, cl, o);
            rl += __shfl_down_sync(FULL, rl, o);
        }
        if (tid == 0) {
            out[0] = cl / (float)B;
            out[1] = rl / (float)B;
        }
        g_cs[tid] = 0.0;
        g_rs[tid] = 0.0;
        g_np[tid] = 0;
        if (tid == 0) g_arrive = 0;
    }
}

extern "C" void kernel_launch(void* const* d_in, const int* in_sizes, int n_in,
                              void* d_out, int out_size)
{
    const float* cls = (const float*)d_in[0];
    const float* reg = (const float*)d_in[1];
    const float* anc = (const float*)d_in[2];
    const float* ann = (const float*)d_in[3];
    float* out = (float*)d_out;

    const int A = in_sizes[2] / 4;            // anchors [1,A,4]
    const int B = in_sizes[1] / (A * 4);      // regressions [B,A,4]
    const int C = in_sizes[0] / (B * A);      // classifications [B,A,C]
    const int M = in_sizes[3] / (B * 5);      // annotations [B,M,5]

    dim3 block(TPB);
    dim3 grid((A + TPB - 1) / TPB, B);
    const int nblocks = grid.x * grid.y;

    if (M == 32 && C == 20)
        fl_kernel<32, 20><<<grid, block>>>(cls, reg, anc, ann, out, A, C, M, B, nblocks);
    else
        fl_kernel<0, 0><<<grid, block>>>(cls, reg, anc, ann, out, A, C, M, B, nblocks);
}

// round 10
// speedup vs baseline: 1.1631x; 1.0065x over previous
#include <cuda_runtime.h>
#include <cfloat>
#include <stdint.h>
#include <math.h>

// ---------------------------------------------------------------------------
// FocalLoss (RetinaNet) fully-fused single-kernel for GB300, v9.
//   v8 core (FSETP/FSEL argmax, streamed cls, 6 blocks/SM) plus:
//   - focal in lg2 domain: p*sqrt.approx(p)*lg2(1-p), single -0.8*ln2 scale
//     (7 -> 5 instrs per class)
//   - branch-free focal (mask with FSEL; every warp ran it anyway)
//   - REDUX.SUM for the positive count
// ---------------------------------------------------------------------------

#define TPB 256
#define M_MAX 64
#define B_MAX 32
#define LN2F 0.69314718055994530942f

__device__ double g_cs[B_MAX];
__device__ double g_rs[B_MAX];
__device__ int    g_np[B_MAX];
__device__ int    g_arrive = 0;

__device__ __forceinline__ float fsqrt_ap(float x) {
    float r; asm("sqrt.approx.f32 %0, %1;" : "=f"(r) : "f"(x)); return r;
}

template <int MT, int CT>
__global__ void __launch_bounds__(TPB, 6)
fl_kernel(const float* __restrict__ cls,
          const float* __restrict__ reg,
          const float* __restrict__ anc,
          const float* __restrict__ ann,
          float* __restrict__ out,
          int A, int C, int M, int B, int nblocks)
{
    __shared__ float4 sbox[M_MAX];   // (x1, y1, x2, y2)
    __shared__ float  sarea[M_MAX];
    __shared__ int    slbl[M_MAX];
    __shared__ bool   s_last;

    const int b   = blockIdx.y;
    const int tid = threadIdx.x;
    const int MM  = MT ? MT : M;
    const unsigned FULL = 0xFFFFFFFFu;

    // ---- load GT boxes (invalid -> degenerate zero box, never selected) ----
    if (tid < MM) {
        const float* g = ann + ((size_t)b * MM + tid) * 5;
        float x1 = g[0], y1 = g[1], x2 = g[2], y2 = g[3];
        const float l = g[4];
        if (l == -1.0f) { x1 = 0.f; y1 = 0.f; x2 = 0.f; y2 = 0.f; }
        sbox[tid]  = make_float4(x1, y1, x2, y2);
        sarea[tid] = (x2 - x1) * (y2 - y1);
        slbl[tid]  = (int)l;
    }
    __syncthreads();

    const int a = blockIdx.x * TPB + tid;

    float cls_acc = 0.0f;
    float reg_acc = 0.0f;
    int   pos_i   = 0;

    if (a < A) {
        const float4 ab = ((const float4*)anc)[a];
        const float aw = ab.z - ab.x;
        const float ah = ab.w - ab.y;
        const float area_a = aw * ah;

        const float* cp = cls + ((size_t)b * A + a) * (CT ? CT : C);

        // --- IoU max/argmax, cancelled cross-multiply compare ---
        // iou_m = inter_m / (S_m - inter_m), S_m = area_a + area_b[m]
        // iou_i > iou_j  <=>  inter_i*S_j > inter_j*S_i
        float binter = 0.0f;
        float bS     = 1.0f;
        int   arg    = 0;
        #pragma unroll
        for (int m = 0; m < MM; m++) {
            const float4 g = sbox[m];
            const float iw = fminf(ab.z, g.z) - fmaxf(ab.x, g.x);
            const float ih = fminf(ab.w, g.w) - fmaxf(ab.y, g.y);
            const float inter = fmaxf(iw, 0.0f) * fmaxf(ih, 0.0f);
            const float S = area_a + sarea[m];
            if (inter * bS > binter * S) {
                binter = inter; bS = S; arg = m;
            }
        }
        const float best = binter / (bS - binter);    // one precise division
        const bool  pos  = (best >= 0.5f);
        const bool  contrib = pos || (best < 0.4f);

        // --- branch-free focal: s = sum p*sqrt(p) * lg2(1-p), scale once ---
        float s = 0.0f;
        if (CT == 20) {
            const float4* cp4 = (const float4*)cp;
            #pragma unroll
            for (int i = 0; i < 5; i++) {
                const float4 v = cp4[i];
                float p;
                p = v.x; s = fmaf(p * fsqrt_ap(p), __log2f(1.0f - p), s);
                p = v.y; s = fmaf(p * fsqrt_ap(p), __log2f(1.0f - p), s);
                p = v.z; s = fmaf(p * fsqrt_ap(p), __log2f(1.0f - p), s);
                p = v.w; s = fmaf(p * fsqrt_ap(p), __log2f(1.0f - p), s);
            }
        } else {
            for (int c = 0; c < C; c++) {
                const float p = fminf(fmaxf(cp[c], 1e-8f), 1.0f - 1e-8f);
                s = fmaf(p * fsqrt_ap(p), __log2f(1.0f - p), s);
            }
        }
        cls_acc = contrib ? (-0.8f * LN2F) * s : 0.0f;

        if (pos) {
            pos_i = 1;
            const int lbl = slbl[arg];
            const float pl = cp[lbl];                  // L1-hot reload
            const float ql = 1.0f - pl;
            // remove the label's negative lg2-term, add its positive term
            const float base = s - pl * fsqrt_ap(pl) * __log2f(ql);
            const float post = ql * fsqrt_ap(ql) * __log2f(pl);
            cls_acc = -LN2F * fmaf(0.8f, base, 0.2f * post);

            // --- smooth-L1 regression loss ---
            const float4 gb = sbox[arg];
            const float gwr = gb.z - gb.x, ghr = gb.w - gb.y;
            const float gcx = gb.x + 0.5f * gwr;
            const float gcy = gb.y + 0.5f * ghr;
            const float gw  = fmaxf(gwr, 1.0f);
            const float gh  = fmaxf(ghr, 1.0f);
            const float acx = ab.x + 0.5f * aw;
            const float acy = ab.y + 0.5f * ah;

            const float t0 = ((gcx - acx) / aw) / 0.1f;
            const float t1 = ((gcy - acy) / ah) / 0.1f;
            const float t2 = logf(gw / aw) / 0.2f;
            const float t3 = logf(gh / ah) / 0.2f;

            const float4 rg = ((const float4*)reg)[(size_t)b * A + a];

            const float thr = 1.0f / 9.0f;
            const float off = 0.5f / 9.0f;
            float sr = 0.0f, d;
            d = fabsf(t0 - rg.x); sr += (d <= thr) ? 4.5f * d * d : d - off;
            d = fabsf(t1 - rg.y); sr += (d <= thr) ? 4.5f * d * d : d - off;
            d = fabsf(t2 - rg.z); sr += (d <= thr) ? 4.5f * d * d : d - off;
            d = fabsf(t3 - rg.w); sr += (d <= thr) ? 4.5f * d * d : d - off;
            reg_acc = sr;
        }
    }

    // ---- block reduction: warp shuffle/REDUX -> shared -> fp64 atomics ----
    #pragma unroll
    for (int o = 16; o > 0; o >>= 1) {
        cls_acc += __shfl_down_sync(FULL, cls_acc, o);
        reg_acc += __shfl_down_sync(FULL, reg_acc, o);
    }
    pos_i = __reduce_add_sync(FULL, (unsigned)pos_i);

    __shared__ float wc[TPB / 32], wr[TPB / 32];
    __shared__ int   wp[TPB / 32];
    const int wid = tid >> 5;
    const int lid = tid & 31;
    if (lid == 0) { wc[wid] = cls_acc; wr[wid] = reg_acc; wp[wid] = pos_i; }
    __syncthreads();

    if (tid < 32) {
        const int nwarp = TPB / 32;
        float csum = (lid < nwarp) ? wc[lid] : 0.0f;
        float rsum = (lid < nwarp) ? wr[lid] : 0.0f;
        int   psum = (lid < nwarp) ? wp[lid] : 0;
        #pragma unroll
        for (int o = 4; o > 0; o >>= 1) {
            csum += __shfl_down_sync(FULL, csum, o);
            rsum += __shfl_down_sync(FULL, rsum, o);
        }
        psum = __reduce_add_sync(FULL, (unsigned)psum);
        if (lid == 0) {
            if (csum != 0.0f) atomicAdd(&g_cs[b], (double)csum);
            if (rsum != 0.0f) atomicAdd(&g_rs[b], (double)rsum);
            if (psum != 0)    atomicAdd(&g_np[b], psum);
            __threadfence();
            const int prev = atomicAdd(&g_arrive, 1);
            s_last = (prev == nblocks - 1);
        }
    }
    __syncthreads();

    // ---- last block finalizes the output and resets the accumulators ----
    if (s_last && tid < 32) {
        float cl = 0.0f, rl = 0.0f;
        if (tid < B) {
            int nvv = 0;
            for (int m = 0; m < M; m++)
                nvv += (ann[((size_t)tid * M + m) * 5 + 4] != -1.0f) ? 1 : 0;
            const int np = g_np[tid];
            const float npf = (float)np;
            cl = (float)g_cs[tid] / fmaxf(npf, 1.0f);
            rl = (float)g_rs[tid] / fmaxf(4.0f * npf, 1.0f);
            if (np == 0) rl = 0.0f;
            if (nvv == 0) { cl = 0.0f; rl = 0.0f; }
        }
        #pragma unroll
        for (int o = 16; o > 0; o >>= 1) {
            cl += __shfl_down_sync(FULL, cl, o);
            rl += __shfl_down_sync(FULL, rl, o);
        }
        if (tid == 0) {
            out[0] = cl / (float)B;
            out[1] = rl / (float)B;
        }
        g_cs[tid] = 0.0;
        g_rs[tid] = 0.0;
        g_np[tid] = 0;
        if (tid == 0) g_arrive = 0;
    }
}

extern "C" void kernel_launch(void* const* d_in, const int* in_sizes, int n_in,
                              void* d_out, int out_size)
{
    const float* cls = (const float*)d_in[0];
    const float* reg = (const float*)d_in[1];
    const float* anc = (const float*)d_in[2];
    const float* ann = (const float*)d_in[3];
    float* out = (float*)d_out;

    const int A = in_sizes[2] / 4;            // anchors [1,A,4]
    const int B = in_sizes[1] / (A * 4);      // regressions [B,A,4]
    const int C = in_sizes[0] / (B * A);      // classifications [B,A,C]
    const int M = in_sizes[3] / (B * 5);      // annotations [B,M,5]

    dim3 block(TPB);
    dim3 grid((A + TPB - 1) / TPB, B);
    const int nblocks = grid.x * grid.y;

    if (M == 32 && C == 20)
        fl_kernel<32, 20><<<grid, block>>>(cls, reg, anc, ann, out, A, C, M, B, nblocks);
    else
        fl_kernel<0, 0><<<grid, block>>>(cls, reg, anc, ann, out, A, C, M, B, nblocks);
}